// round 10
// baseline (speedup 1.0000x reference)
#include <cuda_runtime.h>
#include <math.h>

// Spherization, per row r (512 features):
//   ang_j = A*sigmoid(scaling*x) + phiL
//   out[k]   = radius * prod_{j<k}(sin(ang_j)+eps) * sgn(cos_k)*(|cos(ang_k)|+eps)
//   out[512] = radius * prod_j (sin(ang_j)+eps)
// R6 compute pipeline (MUFU.TANH sigmoid, MUFU.SIN/COS) — the measured-best
// element math — with the SMEM store-staging removed: outputs go straight
// from registers to GMEM as scalar STG.32 (the 4 m-stores of each j-block
// jointly cover a contiguous 512B span; L2 merges them into full sectors).
// One warp per row; lane owns k = 128j+4l+m; 4 chained warp scans.

#define NFEAT 512
#define ROW_OUT 513
#define WARPS_PER_BLOCK 8
#define EPSf 1e-6f

__global__ __launch_bounds__(WARPS_PER_BLOCK * 32)
void spherization_kernel(const float* __restrict__ x,
                         const float* __restrict__ scaling_p,
                         const float* __restrict__ radius_p,
                         float* __restrict__ out,
                         int nrows, float halfA, float mid)
{
    const int wib  = threadIdx.x >> 5;
    const int lane = threadIdx.x & 31;
    const int row  = blockIdx.x * WARPS_PER_BLOCK + wib;
    if (row >= nrows) return;

    const float scaling = __ldg(scaling_p);
    const float radius  = __ldg(radius_p);
    const float hmul = 0.5f * scaling;     // t = hmul*x ; u = tanh(t)

    const float4* xr = reinterpret_cast<const float4*>(x + (size_t)row * NFEAT);
    float* orow = out + (size_t)row * ROW_OUT;

    // prefetch all loads (MLP=4), coalesced LDG.128
    float4 v[4];
    #pragma unroll
    for (int j = 0; j < 4; j++) v[j] = xr[lane + 32 * j];

    float carry = radius;   // radius * (product of all elements in completed blocks)

    #pragma unroll
    for (int j = 0; j < 4; j++) {
        float vv[4] = {v[j].x, v[j].y, v[j].z, v[j].w};
        float sv[4], cv[4];
        #pragma unroll
        for (int m = 0; m < 4; m++) {
            float t = vv[m] * hmul;
            float u;  asm("tanh.approx.f32 %0, %1;" : "=f"(u) : "f"(t));
            float ang = fmaf(halfA, u, mid);          // in [phiL, pi - phiL]
            float sn  = __sinf(ang);                  // > 0 on range
            float cs  = __cosf(ang);
            sv[m] = sn + EPSf;
            cv[m] = copysignf(fabsf(cs) + EPSf, cs);
        }
        // local exclusive prefixes within the 4 owned elements
        float e1  = sv[0];
        float e2  = e1 * sv[1];
        float e3  = e2 * sv[2];
        float tot = e3 * sv[3];

        // warp-inclusive scan of per-lane block totals
        float incl = tot;
        #pragma unroll
        for (int d = 1; d < 32; d <<= 1) {
            float t2 = __shfl_up_sync(0xFFFFFFFFu, incl, d);
            if (lane >= d) incl *= t2;
        }
        float excl = __shfl_up_sync(0xFFFFFFFFu, incl, 1);
        if (lane == 0) excl = 1.0f;

        float bp = carry * excl;  // radius * prod of everything before this lane

        // direct scalar stores: k = 128j + 4*lane + m (contiguous per lane;
        // warp jointly covers the 512B span of this j-block)
        float* op = orow + 128 * j + 4 * lane;
        op[0] = bp * cv[0];
        op[1] = (bp * e1) * cv[1];
        op[2] = (bp * e2) * cv[2];
        op[3] = (bp * e3) * cv[3];

        carry *= __shfl_sync(0xFFFFFFFFu, incl, 31);
    }
    if (lane == 0) orow[NFEAT] = carry;   // out[512] = radius * full product
}

extern "C" void kernel_launch(void* const* d_in, const int* in_sizes, int n_in,
                              void* d_out, int out_size)
{
    int xi = 0;
    for (int i = 0; i < n_in; i++) if (in_sizes[i] > in_sizes[xi]) xi = i;
    int others[2]; int no = 0;
    for (int i = 0; i < n_in && no < 2; i++) if (i != xi) others[no++] = i;

    const float* x   = (const float*)d_in[xi];
    const float* sc  = (const float*)d_in[others[0]];   // scaling
    const float* rad = (const float*)d_in[others[1]];   // radius

    float* out = (float*)d_out;
    int nrows = in_sizes[xi] / NFEAT;

    // constants in double; PI truncated exactly as in the reference
    const double PI_d = 3.141592;
    double phiL = asin(pow(1e-6, 1.0 / 512.0));
    double phiU = PI_d / 2.0 * (1.0 - 0.01);
    if (phiU < phiL) phiL = phiU;
    double A = PI_d - 2.0 * phiL;
    float halfA = (float)(0.5 * A);          // ang = halfA*u + (halfA + phiL)
    float mid   = (float)(0.5 * A + phiL);

    int blocks = (nrows + WARPS_PER_BLOCK - 1) / WARPS_PER_BLOCK;
    spherization_kernel<<<blocks, WARPS_PER_BLOCK * 32>>>(
        x, sc, rad, out, nrows, halfA, mid);
}

// round 11
// speedup vs baseline: 1.3173x; 1.3173x over previous
#include <cuda_runtime.h>
#include <math.h>

// Spherization, per row r (512 features):
//   ang_j = A*sigmoid(scaling*x) + phiL
//   out[k]   = radius * prod_{j<k}(sin(ang_j)+eps) * sgn(cos_k)*(|cos(ang_k)|+eps)
//   out[512] = radius * prod_j (sin(ang_j)+eps)
// R6/R8 compute pipeline (MUFU.TANH sigmoid, MUFU.SIN/COS; measured best),
// SMEM-staged output (mandatory: stores must be per-instruction contiguous),
// readback vectorized to STG.64 with row-parity phase correction:
//   row even: base%8==0 -> pairs (2m,2m+1), scalar k=512
//   row odd : base%8==4 -> scalar k=0, pairs (2m+1,2m+2)  [(base+4)%8==0]

#define NFEAT 512
#define ROW_OUT 513
#define SROW_PITCH 520   // floats; 16B-aligned per-warp rows
#define WARPS_PER_BLOCK 8
#define EPSf 1e-6f

__global__ __launch_bounds__(WARPS_PER_BLOCK * 32)
void spherization_kernel(const float* __restrict__ x,
                         const float* __restrict__ scaling_p,
                         const float* __restrict__ radius_p,
                         float* __restrict__ out,
                         int nrows, float halfA, float mid)
{
    __shared__ float sbuf[WARPS_PER_BLOCK * SROW_PITCH];

    const int wib  = threadIdx.x >> 5;
    const int lane = threadIdx.x & 31;
    const int row  = blockIdx.x * WARPS_PER_BLOCK + wib;
    if (row >= nrows) return;

    const float scaling = __ldg(scaling_p);
    const float radius  = __ldg(radius_p);
    const float hmul = 0.5f * scaling;     // t = hmul*x ; u = tanh(t)

    const float4* xr = reinterpret_cast<const float4*>(x + (size_t)row * NFEAT);
    float* srow = sbuf + wib * SROW_PITCH;

    // prefetch all loads (MLP=4), coalesced LDG.128
    float4 v[4];
    #pragma unroll
    for (int j = 0; j < 4; j++) v[j] = xr[lane + 32 * j];

    float carry = radius;   // radius * (product of all elements in completed blocks)

    #pragma unroll
    for (int j = 0; j < 4; j++) {
        float vv[4] = {v[j].x, v[j].y, v[j].z, v[j].w};
        float sv[4], cv[4];
        #pragma unroll
        for (int m = 0; m < 4; m++) {
            float t = vv[m] * hmul;
            float u;  asm("tanh.approx.f32 %0, %1;" : "=f"(u) : "f"(t));
            float ang = fmaf(halfA, u, mid);          // in [phiL, pi - phiL]
            float sn  = __sinf(ang);                  // > 0 on range
            float cs  = __cosf(ang);
            sv[m] = sn + EPSf;
            cv[m] = copysignf(fabsf(cs) + EPSf, cs);
        }
        // local exclusive prefixes within the 4 owned elements
        float e1  = sv[0];
        float e2  = e1 * sv[1];
        float e3  = e2 * sv[2];
        float tot = e3 * sv[3];

        // warp-inclusive scan of per-lane block totals
        float incl = tot;
        #pragma unroll
        for (int d = 1; d < 32; d <<= 1) {
            float t2 = __shfl_up_sync(0xFFFFFFFFu, incl, d);
            if (lane >= d) incl *= t2;
        }
        float excl = __shfl_up_sync(0xFFFFFFFFu, incl, 1);
        if (lane == 0) excl = 1.0f;

        float bp = carry * excl;  // radius * prod of everything before this lane

        float4 o;
        o.x = bp * cv[0];
        o.y = (bp * e1) * cv[1];
        o.z = (bp * e2) * cv[2];
        o.w = (bp * e3) * cv[3];
        reinterpret_cast<float4*>(srow)[lane + 32 * j] = o;

        carry *= __shfl_sync(0xFFFFFFFFu, incl, 31);
    }
    if (lane == 0) srow[NFEAT] = carry;   // out[512] = radius * full product
    __syncwarp();

    // coalesced SMEM -> GMEM readback, STG.64 with parity phase
    float* orow = out + (size_t)row * ROW_OUT;
    if ((row & 1) == 0) {
        // base % 8 == 0 : pairs (2m, 2m+1), m = lane + 32i
        const float2* s2 = reinterpret_cast<const float2*>(srow);  // 16B-aligned
        #pragma unroll
        for (int i = 0; i < 8; i++) {
            int m = lane + 32 * i;
            *reinterpret_cast<float2*>(orow + 2 * m) = s2[m];
        }
        if (lane == 0) orow[NFEAT] = srow[NFEAT];
    } else {
        // base % 8 == 4 : scalar k=0, then pairs (2m+1, 2m+2)
        if (lane == 0) orow[0] = srow[0];
        #pragma unroll
        for (int i = 0; i < 8; i++) {
            int m = lane + 32 * i;
            float2 p = make_float2(srow[2 * m + 1], srow[2 * m + 2]);
            *reinterpret_cast<float2*>(orow + 2 * m + 1) = p;
        }
    }
}

extern "C" void kernel_launch(void* const* d_in, const int* in_sizes, int n_in,
                              void* d_out, int out_size)
{
    int xi = 0;
    for (int i = 0; i < n_in; i++) if (in_sizes[i] > in_sizes[xi]) xi = i;
    int others[2]; int no = 0;
    for (int i = 0; i < n_in && no < 2; i++) if (i != xi) others[no++] = i;

    const float* x   = (const float*)d_in[xi];
    const float* sc  = (const float*)d_in[others[0]];   // scaling
    const float* rad = (const float*)d_in[others[1]];   // radius

    float* out = (float*)d_out;
    int nrows = in_sizes[xi] / NFEAT;

    // constants in double; PI truncated exactly as in the reference
    const double PI_d = 3.141592;
    double phiL = asin(pow(1e-6, 1.0 / 512.0));
    double phiU = PI_d / 2.0 * (1.0 - 0.01);
    if (phiU < phiL) phiL = phiU;
    double A = PI_d - 2.0 * phiL;
    float halfA = (float)(0.5 * A);          // ang = halfA*u + (halfA + phiL)
    float mid   = (float)(0.5 * A + phiL);

    int blocks = (nrows + WARPS_PER_BLOCK - 1) / WARPS_PER_BLOCK;
    spherization_kernel<<<blocks, WARPS_PER_BLOCK * 32>>>(
        x, sc, rad, out, nrows, halfA, mid);
}

// round 12
// speedup vs baseline: 1.3229x; 1.0042x over previous
#include <cuda_runtime.h>
#include <math.h>

// Spherization, per row r (512 features):
//   ang_j = A*sigmoid(scaling*x) + phiL
//   out[k]   = radius * prod_{j<k}(sin(ang_j)+eps) * sgn(cos_k)*(|cos(ang_k)|+eps)
//   out[512] = radius * prod_j (sin(ang_j)+eps)
// R6 compute pipeline (MUFU.TANH sigmoid, MUFU.SIN/COS; measured best).
// NO SMEM staging: direct phase-shifted STG.128. Row base byte alignment is
// 4*(row%4); storing the lane's float4 at element k = 128j+4*lane-P (P=row&3)
// is 16B-aligned for every row. The vector is assembled from P neighbor
// elements via shfl_up (P=1,2) or, for P=3, shifted +1 with shfl_down and a
// deferred lane-31 vector. Boundary head/tail handled with aligned scalars.
// Every STG.128 is warp-contiguous (full 512B per instruction).

#define NFEAT 512
#define ROW_OUT 513
#define WARPS_PER_BLOCK 8
#define EPSf 1e-6f

template<int P>
__device__ __forceinline__ void row_proc(const float4* __restrict__ xr,
                                         float* __restrict__ orow,
                                         float hmul, float halfA, float mid,
                                         float radius, int lane)
{
    // prefetch all loads (MLP=4), coalesced LDG.128
    float4 v[4];
    #pragma unroll
    for (int j = 0; j < 4; j++) v[j] = xr[lane + 32 * j];

    float carry = radius;
    float tail0 = 0.0f, tail1 = 0.0f;            // P=1,2: prev block lane31 tail
    float pend1 = 0.0f, pend2 = 0.0f, pend3 = 0.0f;  // P=3: lane31 deferred

    #pragma unroll
    for (int j = 0; j < 4; j++) {
        float vv[4] = {v[j].x, v[j].y, v[j].z, v[j].w};
        float sv[4], cv[4];
        #pragma unroll
        for (int m = 0; m < 4; m++) {
            float t = vv[m] * hmul;
            float u;  asm("tanh.approx.f32 %0, %1;" : "=f"(u) : "f"(t));
            float ang = fmaf(halfA, u, mid);          // in [phiL, pi - phiL]
            float sn  = __sinf(ang);                  // > 0 on range
            float cs  = __cosf(ang);
            sv[m] = sn + EPSf;
            cv[m] = copysignf(fabsf(cs) + EPSf, cs);
        }
        // local exclusive prefixes
        float e1  = sv[0];
        float e2  = e1 * sv[1];
        float e3  = e2 * sv[2];
        float tot = e3 * sv[3];

        // warp-inclusive scan of per-lane block totals
        float incl = tot;
        #pragma unroll
        for (int d = 1; d < 32; d <<= 1) {
            float t2 = __shfl_up_sync(0xFFFFFFFFu, incl, d);
            if (lane >= d) incl *= t2;
        }
        float excl = __shfl_up_sync(0xFFFFFFFFu, incl, 1);
        if (lane == 0) excl = 1.0f;
        float bp = carry * excl;

        float o0 = bp * cv[0];
        float o1 = (bp * e1) * cv[1];
        float o2 = (bp * e2) * cv[2];
        float o3 = (bp * e3) * cv[3];

        if constexpr (P == 0) {
            *reinterpret_cast<float4*>(orow + 128 * j + 4 * lane) =
                make_float4(o0, o1, o2, o3);
        } else if constexpr (P == 1) {
            float t0 = __shfl_up_sync(0xFFFFFFFFu, o3, 1);
            if (lane == 0) t0 = tail0;               // prev block lane31 o3
            if (j > 0 || lane > 0)
                *reinterpret_cast<float4*>(orow + 128 * j + 4 * lane - 1) =
                    make_float4(t0, o0, o1, o2);
            tail0 = __shfl_sync(0xFFFFFFFFu, o3, 31);
            if (j == 0 && lane == 0) { orow[0] = o0; orow[1] = o1; orow[2] = o2; }
        } else if constexpr (P == 2) {
            float t0 = __shfl_up_sync(0xFFFFFFFFu, o2, 1);
            float t1 = __shfl_up_sync(0xFFFFFFFFu, o3, 1);
            if (lane == 0) { t0 = tail0; t1 = tail1; }
            if (j > 0 || lane > 0)
                *reinterpret_cast<float4*>(orow + 128 * j + 4 * lane - 2) =
                    make_float4(t0, t1, o0, o1);
            tail0 = __shfl_sync(0xFFFFFFFFu, o2, 31);
            tail1 = __shfl_sync(0xFFFFFFFFu, o3, 31);
            if (j == 0 && lane == 0) { orow[0] = o0; orow[1] = o1; }
        } else {  // P == 3: shift +1 (cheaper than borrowing 3)
            float b = __shfl_sync(0xFFFFFFFFu, o0, 0);   // this block's element 128j
            if (j > 0 && lane == 31)                     // deferred prev-block vector
                *reinterpret_cast<float4*>(orow + 128 * (j - 1) + 125) =
                    make_float4(pend1, pend2, pend3, b); // k = 128j-3 .. 128j
            float t3 = __shfl_down_sync(0xFFFFFFFFu, o0, 1);  // next lane's o0
            if (lane < 31)
                *reinterpret_cast<float4*>(orow + 128 * j + 4 * lane + 1) =
                    make_float4(o1, o2, o3, t3);
            else { pend1 = o1; pend2 = o2; pend3 = o3; }
            if (j == 0 && lane == 0) orow[0] = o0;
        }

        carry *= __shfl_sync(0xFFFFFFFFu, incl, 31);
    }

    // row tails (all addresses verified 8B/16B aligned for their width)
    if constexpr (P == 0) {
        if (lane == 0) orow[NFEAT] = carry;
    } else if constexpr (P == 1) {
        if (lane == 0)   // tail0 = element 511 (broadcast), carry = element 512
            *reinterpret_cast<float2*>(orow + 511) = make_float2(tail0, carry);
    } else if constexpr (P == 2) {
        if (lane == 0) { // tail0,tail1 = elements 510,511
            *reinterpret_cast<float2*>(orow + 510) = make_float2(tail0, tail1);
            orow[NFEAT] = carry;
        }
    } else {
        if (lane == 31)  // elements 509,510,511,512
            *reinterpret_cast<float4*>(orow + 509) =
                make_float4(pend1, pend2, pend3, carry);
    }
}

__global__ __launch_bounds__(WARPS_PER_BLOCK * 32)
void spherization_kernel(const float* __restrict__ x,
                         const float* __restrict__ scaling_p,
                         const float* __restrict__ radius_p,
                         float* __restrict__ out,
                         int nrows, float halfA, float mid)
{
    const int wib  = threadIdx.x >> 5;
    const int lane = threadIdx.x & 31;
    const int row  = blockIdx.x * WARPS_PER_BLOCK + wib;
    if (row >= nrows) return;

    const float scaling = __ldg(scaling_p);
    const float radius  = __ldg(radius_p);
    const float hmul = 0.5f * scaling;     // t = hmul*x ; u = tanh(t)

    const float4* xr = reinterpret_cast<const float4*>(x + (size_t)row * NFEAT);
    float* orow = out + (size_t)row * ROW_OUT;

    switch (row & 3) {   // == wib & 3 : warp-uniform
        case 0: row_proc<0>(xr, orow, hmul, halfA, mid, radius, lane); break;
        case 1: row_proc<1>(xr, orow, hmul, halfA, mid, radius, lane); break;
        case 2: row_proc<2>(xr, orow, hmul, halfA, mid, radius, lane); break;
        default: row_proc<3>(xr, orow, hmul, halfA, mid, radius, lane); break;
    }
}

extern "C" void kernel_launch(void* const* d_in, const int* in_sizes, int n_in,
                              void* d_out, int out_size)
{
    int xi = 0;
    for (int i = 0; i < n_in; i++) if (in_sizes[i] > in_sizes[xi]) xi = i;
    int others[2]; int no = 0;
    for (int i = 0; i < n_in && no < 2; i++) if (i != xi) others[no++] = i;

    const float* x   = (const float*)d_in[xi];
    const float* sc  = (const float*)d_in[others[0]];   // scaling
    const float* rad = (const float*)d_in[others[1]];   // radius

    float* out = (float*)d_out;
    int nrows = in_sizes[xi] / NFEAT;

    // constants in double; PI truncated exactly as in the reference
    const double PI_d = 3.141592;
    double phiL = asin(pow(1e-6, 1.0 / 512.0));
    double phiU = PI_d / 2.0 * (1.0 - 0.01);
    if (phiU < phiL) phiL = phiU;
    double A = PI_d - 2.0 * phiL;
    float halfA = (float)(0.5 * A);          // ang = halfA*u + (halfA + phiL)
    float mid   = (float)(0.5 * A + phiL);

    int blocks = (nrows + WARPS_PER_BLOCK - 1) / WARPS_PER_BLOCK;
    spherization_kernel<<<blocks, WARPS_PER_BLOCK * 32>>>(
        x, sc, rad, out, nrows, halfA, mid);
}